// round 10
// baseline (speedup 1.0000x reference)
#include <cuda_runtime.h>
#include <cuda_fp16.h>
#include <math.h>
#include <stdint.h>

#define NPTS   32768
#define NE     1024
#define EDIM   256
#define ZSIZE  8388608
#define OUT_ZQ   1
#define OUT_PERP (1 + ZSIZE)
#define OUT_IDX  (2 + ZSIZE)
#define MARGIN   1.0e-3f
#define CAP      32

__device__ float  g_zt[NPTS * EDIM];       // 32MB transposed z
__device__ int    g_ccnt[NPTS];
__device__ int    g_cand[NPTS * CAP];      // 4MB candidate codes
__device__ int    g_idx[NPTS];
__device__ float  g_enorm[NE];
__device__ int    g_counts[NE];
__device__ float  g_loss_sum;

__device__ __forceinline__ uint32_t encF(float f) {
    uint32_t u = __float_as_uint(f);
    return (u & 0x80000000u) ? ~u : (u | 0x80000000u);
}
__device__ __forceinline__ float decF(uint32_t u) {
    u = (u & 0x80000000u) ? (u & 0x7FFFFFFFu) : ~u;
    return __uint_as_float(u);
}
__device__ __forceinline__ uint32_t pk2h(float a, float b) {
    __half2 h = __floats2half2_rn(a, b);
    return *(uint32_t*)&h;
}

#define MMA_F16(d, a, b) \
    asm volatile("mma.sync.aligned.m16n8k16.row.col.f32.f16.f16.f32 " \
        "{%0,%1,%2,%3}, {%4,%5,%6,%7}, {%8,%9}, {%0,%1,%2,%3};" \
        : "+f"((d)[0]), "+f"((d)[1]), "+f"((d)[2]), "+f"((d)[3]) \
        : "r"((a)[0]), "r"((a)[1]), "r"((a)[2]), "r"((a)[3]), \
          "r"((b)[0]), "r"((b)[1]))

// ======================= transpose: z (B,C,H,W) -> z_t (N, C) =======================
__global__ __launch_bounds__(256) void transpose_kernel(const float* __restrict__ z) {
    __shared__ float tile[256 * 33];
    int t = threadIdx.x;
    int n0 = blockIdx.x * 32;
    int b = n0 >> 10, hw0 = n0 & 1023;
    const float* zb = z + (size_t)b * 262144 + hw0;
#pragma unroll
    for (int i = 0; i < 8; i++) {
        int idx = t + i * 256;
        int c = idx >> 3, q = idx & 7;
        float4 v = *(const float4*)(zb + (size_t)c * 1024 + q * 4);
        tile[c * 33 + q * 4 + 0] = v.x; tile[c * 33 + q * 4 + 1] = v.y;
        tile[c * 33 + q * 4 + 2] = v.z; tile[c * 33 + q * 4 + 3] = v.w;
    }
    __syncthreads();
#pragma unroll
    for (int i = 0; i < 8; i++) {
        int idx = t + i * 256;
        int m = idx >> 6, c4 = idx & 63;
        float4 o;
        o.x = tile[(c4 * 4 + 0) * 33 + m]; o.y = tile[(c4 * 4 + 1) * 33 + m];
        o.z = tile[(c4 * 4 + 2) * 33 + m]; o.w = tile[(c4 * 4 + 3) * 33 + m];
        *(float4*)(g_zt + (size_t)(n0 + m) * 256 + c4 * 4) = o;
    }
}

// ======================= enorm: exact ||e||^2 + zero accumulators =======================
__global__ void enorm_kernel(const float* __restrict__ w) {
    int c = blockIdx.x * blockDim.x + threadIdx.x;
    g_counts[c] = 0;
    if (c == 0) g_loss_sum = 0.f;
    const float* row = w + (size_t)c * EDIM;
    float s = 0.f;
#pragma unroll 8
    for (int k = 0; k < EDIM; k++) {
        float v = row[k];
        s = __fadd_rn(s, __fmul_rn(v, v));
    }
    g_enorm[c] = s;
}

// ======================= fp16 HMMA GEMM + fused candidate selection ============
// 512 threads (16 warps 4x4). CTA: 128 points x 1024 codes (8 tiles of 128).
// No score materialization: per tile, scores fold into smem prefix-min
// (atomicMin), then threshold vs prefix_min+MARGIN appends candidate codes.
// Any-subset-min + MARGIN >= 2*err guarantees the true argmin is captured.
#define AST2 264
#define BST2 40
#define A_HL (128 * AST2)
#define B_HL (128 * BST2)
#define SMEM_MMA (A_HL * 2 + 2 * B_HL * 2 + 1024 * 4 + 512 + 512 + 128 * CAP * 4)

__global__ __launch_bounds__(512, 1)
void mma_kernel(const float* __restrict__ w) {
    extern __shared__ __half smh[];
    __half* A_s = smh;
    __half* B_s = smh + A_HL;                          // [2][B_HL]
    float*  sw_s = (float*)(smh + A_HL + 2 * B_HL);    // [1024]
    uint32_t* smin = (uint32_t*)(sw_s + 1024);         // [128]
    int* ccnt = (int*)(smin + 128);                    // [128]
    int* cand = (int*)(ccnt + 128);                    // [128][CAP]

    int tid = threadIdx.x;
    int lane = tid & 31, wid = tid >> 5;
    int g = lane >> 2, t = lane & 3;
    int wm = wid >> 2, wn = wid & 3;
    int n0 = blockIdx.x * 128;

    if (tid < 128) { smin[tid] = 0xFFFFFFFFu; ccnt[tid] = 0; }
    for (int i = tid; i < NE; i += 512) sw_s[i] = g_enorm[i];

    // A fill: 128 x 256 fp32 -> fp16
#pragma unroll
    for (int i = 0; i < 16; i++) {
        int idx = tid + i * 512;
        int m = idx >> 6, c4 = (idx & 63) << 2;
        float4 v = *(const float4*)(g_zt + (size_t)(n0 + m) * 256 + c4);
        uint2 h;
        h.x = pk2h(v.x, v.y); h.y = pk2h(v.z, v.w);
        *(uint2*)(A_s + m * AST2 + c4) = h;
    }

    int c0 = tid >> 3, kq0 = (tid & 7) << 2;
    int c1 = (tid + 512) >> 3, kq1 = ((tid + 512) & 7) << 2;

    for (int j = 0; j < 8; j++) {
        float acc[2][4][4];
#pragma unroll
        for (int mt = 0; mt < 2; mt++)
#pragma unroll
            for (int nt = 0; nt < 4; nt++)
#pragma unroll
                for (int q = 0; q < 4; q++) acc[mt][nt][q] = 0.f;

        {   // prologue: B chunk kc=0 -> buf 0
            const float* wp = w + (size_t)(j * 128) * 256;
            float4 v0 = *(const float4*)(wp + (size_t)c0 * 256 + kq0);
            float4 v1 = *(const float4*)(wp + (size_t)c1 * 256 + kq1);
            uint2 h0, h1;
            h0.x = pk2h(v0.x, v0.y); h0.y = pk2h(v0.z, v0.w);
            h1.x = pk2h(v1.x, v1.y); h1.y = pk2h(v1.z, v1.w);
            *(uint2*)(B_s + c0 * BST2 + kq0) = h0;
            *(uint2*)(B_s + c1 * BST2 + kq1) = h1;
        }
        __syncthreads();

        for (int kc = 0; kc < 8; kc++) {
            int buf = kc & 1;
            float4 pf0, pf1;
            if (kc < 7) {
                const float* wp = w + (size_t)(j * 128) * 256 + (kc + 1) * 32;
                pf0 = *(const float4*)(wp + (size_t)c0 * 256 + kq0);
                pf1 = *(const float4*)(wp + (size_t)c1 * 256 + kq1);
            }
            const __half* Bb = B_s + buf * B_HL;
#pragma unroll
            for (int ks = 0; ks < 2; ks++) {
                int koff = ks * 16;
                uint32_t bf[4][2];
#pragma unroll
                for (int nt = 0; nt < 4; nt++) {
                    int code = wn * 32 + nt * 8 + g;
                    bf[nt][0] = *(const uint32_t*)(Bb + code * BST2 + koff + 2 * t);
                    bf[nt][1] = *(const uint32_t*)(Bb + code * BST2 + koff + 2 * t + 8);
                }
#pragma unroll
                for (int mt = 0; mt < 2; mt++) {
                    int row = wm * 32 + mt * 16 + g;
                    int k0 = kc * 32 + koff;
                    uint32_t af[4];
                    af[0] = *(const uint32_t*)(A_s + row * AST2 + k0 + 2 * t);
                    af[1] = *(const uint32_t*)(A_s + (row + 8) * AST2 + k0 + 2 * t);
                    af[2] = *(const uint32_t*)(A_s + row * AST2 + k0 + 2 * t + 8);
                    af[3] = *(const uint32_t*)(A_s + (row + 8) * AST2 + k0 + 2 * t + 8);
#pragma unroll
                    for (int nt = 0; nt < 4; nt++)
                        MMA_F16(acc[mt][nt], af, bf[nt]);
                }
            }
            if (kc < 7) {
                uint2 h0, h1;
                h0.x = pk2h(pf0.x, pf0.y); h0.y = pk2h(pf0.z, pf0.w);
                h1.x = pk2h(pf1.x, pf1.y); h1.y = pk2h(pf1.z, pf1.w);
                *(uint2*)(B_s + (buf ^ 1) * B_HL + c0 * BST2 + kq0) = h0;
                *(uint2*)(B_s + (buf ^ 1) * B_HL + c1 * BST2 + kq1) = h1;
            }
            __syncthreads();
        }

        // ---- epilogue phase 1: scores -> registers, per-row tile min ----
        float sreg[2][4][4];
        float tmin[4] = {3.4e38f, 3.4e38f, 3.4e38f, 3.4e38f};
#pragma unroll
        for (int nt = 0; nt < 4; nt++) {
            int colg = j * 128 + wn * 32 + nt * 8 + 2 * t;
            float sw0 = sw_s[colg], sw1 = sw_s[colg + 1];
#pragma unroll
            for (int mt = 0; mt < 2; mt++) {
                float s00 = fmaf(-2.f, acc[mt][nt][0], sw0);
                float s01 = fmaf(-2.f, acc[mt][nt][1], sw1);
                float s10 = fmaf(-2.f, acc[mt][nt][2], sw0);
                float s11 = fmaf(-2.f, acc[mt][nt][3], sw1);
                sreg[mt][nt][0] = s00; sreg[mt][nt][1] = s01;
                sreg[mt][nt][2] = s10; sreg[mt][nt][3] = s11;
                tmin[mt * 2]     = fminf(tmin[mt * 2],     fminf(s00, s01));
                tmin[mt * 2 + 1] = fminf(tmin[mt * 2 + 1], fminf(s10, s11));
            }
        }
#pragma unroll
        for (int r = 0; r < 4; r++) {
            int row = wm * 32 + (r >> 1) * 16 + (r & 1) * 8 + g;
            atomicMin(&smin[row], encF(tmin[r]));
        }
        __syncthreads();

        // ---- epilogue phase 2: threshold vs prefix min, append candidates ----
        float thr[4];
#pragma unroll
        for (int r = 0; r < 4; r++) {
            int row = wm * 32 + (r >> 1) * 16 + (r & 1) * 8 + g;
            thr[r] = decF(smin[row]) + MARGIN;
        }
#pragma unroll
        for (int nt = 0; nt < 4; nt++) {
            int colg = j * 128 + wn * 32 + nt * 8 + 2 * t;
#pragma unroll
            for (int mt = 0; mt < 2; mt++) {
                int r0 = wm * 32 + mt * 16 + g;
                if (sreg[mt][nt][0] <= thr[mt * 2]) {
                    int ps = atomicAdd(&ccnt[r0], 1);
                    if (ps < CAP) cand[r0 * CAP + ps] = colg;
                }
                if (sreg[mt][nt][1] <= thr[mt * 2]) {
                    int ps = atomicAdd(&ccnt[r0], 1);
                    if (ps < CAP) cand[r0 * CAP + ps] = colg + 1;
                }
                if (sreg[mt][nt][2] <= thr[mt * 2 + 1]) {
                    int ps = atomicAdd(&ccnt[r0 + 8], 1);
                    if (ps < CAP) cand[(r0 + 8) * CAP + ps] = colg;
                }
                if (sreg[mt][nt][3] <= thr[mt * 2 + 1]) {
                    int ps = atomicAdd(&ccnt[r0 + 8], 1);
                    if (ps < CAP) cand[(r0 + 8) * CAP + ps] = colg + 1;
                }
            }
        }
        // no sync needed here: later tiles only tighten smin (still a valid
        // subset-min threshold); prologue writes B_s which phase2 never reads
    }
    __syncthreads();

    // flush candidates to global
    if (tid < 128) {
        int cnt = ccnt[tid];
        g_ccnt[n0 + tid] = cnt;
        int lim = (cnt <= CAP) ? cnt : 0;
        for (int i = 0; i < lim; i++)
            g_cand[(size_t)(n0 + tid) * CAP + i] = cand[tid * CAP + i];
    }
}

// ======================= rescore: exact argmin over candidate lists ========
__global__ __launch_bounds__(256) void rescore_kernel(const float* __restrict__ w,
                                                      float* __restrict__ out) {
    __shared__ unsigned long long best[64];
    int tid = threadIdx.x;
    int p = tid >> 2, q = tid & 3;
    int n0 = blockIdx.x * 64;
    int n = n0 + p;

    if (tid < 64) best[tid] = 0xFFFFFFFFFFFFFFFFull;
    __syncthreads();

    int cnt = g_ccnt[n];
    if (cnt > 1) {
        const float* zr = g_zt + (size_t)n * 256;
        if (cnt <= CAP) {
            for (int ci = q; ci < cnt; ci += 4) {
                int code = g_cand[(size_t)n * CAP + ci];
                const float* wr = w + (size_t)code * EDIM;
                float szl = 0.f, dot = 0.f;
#pragma unroll 8
                for (int k = 0; k < EDIM; k++) {
                    float zv = zr[k];
                    szl = __fadd_rn(szl, __fmul_rn(zv, zv));   // exact chain
                    dot = fmaf(zv, wr[k], dot);                // exact chain
                }
                float d = __fsub_rn(__fadd_rn(szl, __ldg(&g_enorm[code])),
                                    __fmul_rn(2.f, dot));
                unsigned long long pk =
                    ((unsigned long long)encF(d) << 32) | (uint32_t)code;
                atomicMin(&best[p], pk);
            }
        } else {   // overflow fallback (≈never): exact full scan
            for (int code = q; code < NE; code += 4) {
                const float* wr = w + (size_t)code * EDIM;
                float szl = 0.f, dot = 0.f;
#pragma unroll 8
                for (int k = 0; k < EDIM; k++) {
                    float zv = zr[k];
                    szl = __fadd_rn(szl, __fmul_rn(zv, zv));
                    dot = fmaf(zv, wr[k], dot);
                }
                float d = __fsub_rn(__fadd_rn(szl, __ldg(&g_enorm[code])),
                                    __fmul_rn(2.f, dot));
                unsigned long long pk =
                    ((unsigned long long)encF(d) << 32) | (uint32_t)code;
                atomicMin(&best[p], pk);
            }
        }
    }
    __syncthreads();
    if (q == 0) {
        int bc = (cnt == 1) ? g_cand[(size_t)n * CAP]
                            : (int)(best[p] & 0xFFFFFFFFu);
        g_idx[n] = bc;
        out[OUT_IDX + n] = (float)bc;
        atomicAdd(&g_counts[bc], 1);
    }
}

// ======================= gather: z_q_out (STE) + loss =======================
__global__ __launch_bounds__(256) void gather_kernel(const float* __restrict__ z,
                                                     const float* __restrict__ w,
                                                     float* __restrict__ out) {
    __shared__ float wrow[32][257];
    __shared__ int ids[32];
    __shared__ float red[8];
    int t = threadIdx.x, lane = t & 31, wrp = t >> 5;
    int n0 = blockIdx.x * 32;
    int b = n0 >> 10, hw0 = n0 & 1023;

    if (t < 32) ids[t] = g_idx[n0 + t];
    __syncthreads();
#pragma unroll
    for (int i = 0; i < 8; i++) {
        int idx = t + i * 256;
        int r = idx >> 6, q = idx & 63;
        float4 v = *(const float4*)(w + (size_t)ids[r] * 256 + q * 4);
        wrow[r][q * 4 + 0] = v.x; wrow[r][q * 4 + 1] = v.y;
        wrow[r][q * 4 + 2] = v.z; wrow[r][q * 4 + 3] = v.w;
    }
    __syncthreads();

    float loss = 0.f;
    const float* zb = z + (size_t)b * 262144 + hw0;
    float* ob = out + OUT_ZQ + (size_t)b * 262144 + hw0;
    for (int c = wrp; c < 256; c += 8) {
        float zv = zb[(size_t)c * 1024 + lane];
        float q = wrow[lane][c];
        float d = __fsub_rn(q, zv);
        ob[(size_t)c * 1024 + lane] = __fadd_rn(zv, d);
        loss += d * d;
    }
#pragma unroll
    for (int off = 16; off; off >>= 1) loss += __shfl_down_sync(0xffffffffu, loss, off);
    if (lane == 0) red[wrp] = loss;
    __syncthreads();
    if (wrp == 0) {
        float v = (lane < 8) ? red[lane] : 0.f;
#pragma unroll
        for (int off = 4; off; off >>= 1) v += __shfl_down_sync(0xffffffffu, v, off);
        if (lane == 0) atomicAdd(&g_loss_sum, v);
    }
}

// ======================= finalize =======================
__global__ void finalize_kernel(float* __restrict__ out) {
    int t = threadIdx.x;
    float em = (float)g_counts[t] * (1.0f / 32768.f);
    float s = em * logf(em + 1e-10f);
#pragma unroll
    for (int off = 16; off; off >>= 1) s += __shfl_down_sync(0xffffffffu, s, off);
    __shared__ float red[32];
    int lane = t & 31, wid = t >> 5;
    if (lane == 0) red[wid] = s;
    __syncthreads();
    if (wid == 0) {
        float v = red[lane];
#pragma unroll
        for (int off = 16; off; off >>= 1) v += __shfl_down_sync(0xffffffffu, v, off);
        if (lane == 0) {
            out[0] = g_loss_sum * (1.25f / 8388608.f);
            out[OUT_PERP] = expf(-v);
        }
    }
}

// ======================= launch =======================
extern "C" void kernel_launch(void* const* d_in, const int* in_sizes, int n_in,
                              void* d_out, int out_size) {
    const float* z = (const float*)d_in[0];
    const float* w = (const float*)d_in[1];
    float* out = (float*)d_out;

    cudaFuncSetAttribute(mma_kernel, cudaFuncAttributeMaxDynamicSharedMemorySize, SMEM_MMA);

    transpose_kernel<<<NPTS / 32, 256>>>(z);
    enorm_kernel<<<4, 256>>>(w);
    mma_kernel<<<NPTS / 128, 512, SMEM_MMA>>>(w);
    rescore_kernel<<<NPTS / 64, 256>>>(w, out);
    gather_kernel<<<NPTS / 32, 256>>>(z, w, out);
    finalize_kernel<<<1, 1024>>>(out);
}

// round 11
// speedup vs baseline: 1.4067x; 1.4067x over previous
#include <cuda_runtime.h>
#include <cuda_fp16.h>
#include <math.h>
#include <stdint.h>

#define NPTS   32768
#define NE     1024
#define EDIM   256
#define ZSIZE  8388608
#define OUT_ZQ   1
#define OUT_PERP (1 + ZSIZE)
#define OUT_IDX  (2 + ZSIZE)
#define MARGIN   1.0e-3f
#define CAP      16

__device__ float  g_zt[NPTS * EDIM];       // 32MB transposed z
__device__ int    g_idx[NPTS];
__device__ float  g_enorm[NE];
__device__ int    g_counts[NE];
__device__ float  g_loss_sum;

__device__ __forceinline__ uint32_t encF(float f) {
    uint32_t u = __float_as_uint(f);
    return (u & 0x80000000u) ? ~u : (u | 0x80000000u);
}
__device__ __forceinline__ float decF(uint32_t u) {
    u = (u & 0x80000000u) ? (u & 0x7FFFFFFFu) : ~u;
    return __uint_as_float(u);
}
__device__ __forceinline__ uint32_t pk2h(float a, float b) {
    __half2 h = __floats2half2_rn(a, b);
    return *(uint32_t*)&h;
}

#define MMA_F16(d, a, b) \
    asm volatile("mma.sync.aligned.m16n8k16.row.col.f32.f16.f16.f32 " \
        "{%0,%1,%2,%3}, {%4,%5,%6,%7}, {%8,%9}, {%0,%1,%2,%3};" \
        : "+f"((d)[0]), "+f"((d)[1]), "+f"((d)[2]), "+f"((d)[3]) \
        : "r"((a)[0]), "r"((a)[1]), "r"((a)[2]), "r"((a)[3]), \
          "r"((b)[0]), "r"((b)[1]))

// ======================= transpose: z (B,C,H,W) -> z_t (N, C) =======================
__global__ __launch_bounds__(256) void transpose_kernel(const float* __restrict__ z) {
    __shared__ float tile[256 * 33];
    int t = threadIdx.x;
    int n0 = blockIdx.x * 32;
    int b = n0 >> 10, hw0 = n0 & 1023;
    const float* zb = z + (size_t)b * 262144 + hw0;
#pragma unroll
    for (int i = 0; i < 8; i++) {
        int idx = t + i * 256;
        int c = idx >> 3, q = idx & 7;
        float4 v = *(const float4*)(zb + (size_t)c * 1024 + q * 4);
        tile[c * 33 + q * 4 + 0] = v.x; tile[c * 33 + q * 4 + 1] = v.y;
        tile[c * 33 + q * 4 + 2] = v.z; tile[c * 33 + q * 4 + 3] = v.w;
    }
    __syncthreads();
#pragma unroll
    for (int i = 0; i < 8; i++) {
        int idx = t + i * 256;
        int m = idx >> 6, c4 = idx & 63;
        float4 o;
        o.x = tile[(c4 * 4 + 0) * 33 + m]; o.y = tile[(c4 * 4 + 1) * 33 + m];
        o.z = tile[(c4 * 4 + 2) * 33 + m]; o.w = tile[(c4 * 4 + 3) * 33 + m];
        *(float4*)(g_zt + (size_t)(n0 + m) * 256 + c4 * 4) = o;
    }
}

// ======================= enorm: exact ||e||^2 + zero accumulators =======================
__global__ void enorm_kernel(const float* __restrict__ w) {
    int c = blockIdx.x * blockDim.x + threadIdx.x;
    g_counts[c] = 0;
    if (c == 0) g_loss_sum = 0.f;
    const float* row = w + (size_t)c * EDIM;
    float s = 0.f;
#pragma unroll 8
    for (int k = 0; k < EDIM; k++) {
        float v = row[k];
        s = __fadd_rn(s, __fmul_rn(v, v));
    }
    g_enorm[c] = s;
}

// ======================= fused: fp16 HMMA GEMM + smem scores + select + exact ========
// 512 threads (16 warps, 2(M) x 8(N)). CTA: 64 points x 1024 codes.
// Scores live in SMEM fp16 (64 x 1032). After GEMM: final-min threshold
// (identical semantics to R9's two-pass), inline exact rescore of candidates.
#define TM    64
#define AST2  264
#define BST2  40
#define SST   1032
#define A_HL  (TM * AST2)              // 16896 halves
#define B_HL  (128 * BST2)             // 5120 halves
#define SC_HL (TM * SST)               // 66048 halves
#define SMEM_MMA (A_HL * 2 + 2 * B_HL * 2 + SC_HL * 2 + 1024 * 4 + 64 * 4 + 64 * 4 + 64 * 8 + 64 * CAP * 4)

__global__ __launch_bounds__(512, 1)
void mma_kernel(const float* __restrict__ w, float* __restrict__ out) {
    extern __shared__ __half smh[];
    __half* A_s  = smh;
    __half* B_s  = smh + A_HL;                      // [2][B_HL]
    __half* sc_s = smh + A_HL + 2 * B_HL;           // [64][SST]
    float*  sw_s = (float*)(sc_s + SC_HL);          // [1024]
    uint32_t* smin = (uint32_t*)(sw_s + 1024);      // [64]
    int* ccnt = (int*)(smin + 64);                  // [64]
    unsigned long long* best = (unsigned long long*)(ccnt + 64);  // [64]
    int* cand = (int*)(best + 64);                  // [64][CAP]

    int tid = threadIdx.x;
    int lane = tid & 31, wid = tid >> 5;
    int g = lane >> 2, t = lane & 3;
    int wm = wid >> 3, wn = wid & 7;
    int n0 = blockIdx.x * TM;

    if (tid < 64) {
        smin[tid] = 0xFFFFFFFFu;
        ccnt[tid] = 0;
        best[tid] = 0xFFFFFFFFFFFFFFFFull;
    }
    for (int i = tid; i < NE; i += 512) sw_s[i] = g_enorm[i];

    // A fill: 64 x 256 fp32 -> fp16
#pragma unroll
    for (int i = 0; i < 8; i++) {
        int idx = tid + i * 512;
        int m = idx >> 6, c4 = (idx & 63) << 2;
        float4 v = *(const float4*)(g_zt + (size_t)(n0 + m) * 256 + c4);
        uint2 h;
        h.x = pk2h(v.x, v.y); h.y = pk2h(v.z, v.w);
        *(uint2*)(A_s + m * AST2 + c4) = h;
    }

    int c0 = tid >> 3, kq0 = (tid & 7) << 2;
    int c1 = (tid + 512) >> 3, kq1 = ((tid + 512) & 7) << 2;

    float rm[4] = {3.4e38f, 3.4e38f, 3.4e38f, 3.4e38f};  // rows wm*32+g, +8, +16, +24

    for (int j = 0; j < 8; j++) {
        float acc[2][2][4];
#pragma unroll
        for (int mt = 0; mt < 2; mt++)
#pragma unroll
            for (int nt = 0; nt < 2; nt++)
#pragma unroll
                for (int q = 0; q < 4; q++) acc[mt][nt][q] = 0.f;

        {   // prologue: B chunk kc=0 -> buf 0
            const float* wp = w + (size_t)(j * 128) * 256;
            float4 v0 = *(const float4*)(wp + (size_t)c0 * 256 + kq0);
            float4 v1 = *(const float4*)(wp + (size_t)c1 * 256 + kq1);
            uint2 h0, h1;
            h0.x = pk2h(v0.x, v0.y); h0.y = pk2h(v0.z, v0.w);
            h1.x = pk2h(v1.x, v1.y); h1.y = pk2h(v1.z, v1.w);
            *(uint2*)(B_s + c0 * BST2 + kq0) = h0;
            *(uint2*)(B_s + c1 * BST2 + kq1) = h1;
        }
        __syncthreads();

        for (int kc = 0; kc < 8; kc++) {
            int buf = kc & 1;
            float4 pf0, pf1;
            if (kc < 7) {
                const float* wp = w + (size_t)(j * 128) * 256 + (kc + 1) * 32;
                pf0 = *(const float4*)(wp + (size_t)c0 * 256 + kq0);
                pf1 = *(const float4*)(wp + (size_t)c1 * 256 + kq1);
            }
            const __half* Bb = B_s + buf * B_HL;
#pragma unroll
            for (int ks = 0; ks < 2; ks++) {
                int koff = ks * 16;
                uint32_t bf[2][2];
#pragma unroll
                for (int nt = 0; nt < 2; nt++) {
                    int code = wn * 16 + nt * 8 + g;
                    bf[nt][0] = *(const uint32_t*)(Bb + code * BST2 + koff + 2 * t);
                    bf[nt][1] = *(const uint32_t*)(Bb + code * BST2 + koff + 2 * t + 8);
                }
#pragma unroll
                for (int mt = 0; mt < 2; mt++) {
                    int row = wm * 32 + mt * 16 + g;
                    int k0 = kc * 32 + koff;
                    uint32_t af[4];
                    af[0] = *(const uint32_t*)(A_s + row * AST2 + k0 + 2 * t);
                    af[1] = *(const uint32_t*)(A_s + (row + 8) * AST2 + k0 + 2 * t);
                    af[2] = *(const uint32_t*)(A_s + row * AST2 + k0 + 2 * t + 8);
                    af[3] = *(const uint32_t*)(A_s + (row + 8) * AST2 + k0 + 2 * t + 8);
#pragma unroll
                    for (int nt = 0; nt < 2; nt++)
                        MMA_F16(acc[mt][nt], af, bf[nt]);
                }
            }
            if (kc < 7) {
                uint2 h0, h1;
                h0.x = pk2h(pf0.x, pf0.y); h0.y = pk2h(pf0.z, pf0.w);
                h1.x = pk2h(pf1.x, pf1.y); h1.y = pk2h(pf1.z, pf1.w);
                *(uint2*)(B_s + (buf ^ 1) * B_HL + c0 * BST2 + kq0) = h0;
                *(uint2*)(B_s + (buf ^ 1) * B_HL + c1 * BST2 + kq1) = h1;
            }
            __syncthreads();
        }

        // epilogue: scores -> smem fp16, fold register min
#pragma unroll
        for (int nt = 0; nt < 2; nt++) {
            int cg = j * 128 + wn * 16 + nt * 8 + 2 * t;
            float sw0 = sw_s[cg], sw1 = sw_s[cg + 1];
#pragma unroll
            for (int mt = 0; mt < 2; mt++) {
                int row0 = wm * 32 + mt * 16 + g;
                float s00 = fmaf(-2.f, acc[mt][nt][0], sw0);
                float s01 = fmaf(-2.f, acc[mt][nt][1], sw1);
                float s10 = fmaf(-2.f, acc[mt][nt][2], sw0);
                float s11 = fmaf(-2.f, acc[mt][nt][3], sw1);
                *(__half2*)(sc_s + row0 * SST + cg) = __floats2half2_rn(s00, s01);
                *(__half2*)(sc_s + (row0 + 8) * SST + cg) = __floats2half2_rn(s10, s11);
                rm[mt * 2]     = fminf(rm[mt * 2],     fminf(s00, s01));
                rm[mt * 2 + 1] = fminf(rm[mt * 2 + 1], fminf(s10, s11));
            }
        }
    }

#pragma unroll
    for (int r = 0; r < 4; r++) {
        int row = wm * 32 + (r >> 1) * 16 + (r & 1) * 8 + g;
        atomicMin(&smin[row], encF(rm[r]));
    }
    __syncthreads();

    // ---- selection: final-min threshold over smem scores (R9 semantics) ----
    {
        int p = tid & 63, s = tid >> 6;           // 8 threads per row, row-major lanes
        float thr = decF(smin[p]) + MARGIN;
        const __half* rowp = sc_s + p * SST + s * 128;
#pragma unroll
        for (int i = 0; i < 16; i++) {
            uint4 v = *(const uint4*)(rowp + i * 8);
            const uint32_t* wd = &v.x;
#pragma unroll
            for (int jw = 0; jw < 4; jw++) {
                float2 f = __half22float2(*(const __half2*)&wd[jw]);
                int cb = s * 128 + i * 8 + jw * 2;
                if (f.x <= thr) {
                    int ps = atomicAdd(&ccnt[p], 1);
                    if (ps < CAP) cand[p * CAP + ps] = cb;
                }
                if (f.y <= thr) {
                    int ps = atomicAdd(&ccnt[p], 1);
                    if (ps < CAP) cand[p * CAP + ps] = cb + 1;
                }
            }
        }
    }
    __syncthreads();

    // ---- exact rescore: 8 threads per point (bit-exact reference chains) ----
    {
        int p = tid >> 3, q = tid & 7;
        int cnt = ccnt[p];
        if (cnt > 1) {
            int n = n0 + p;
            const float* zr = g_zt + (size_t)n * 256;
            if (cnt <= CAP) {
                for (int ci = q; ci < cnt; ci += 8) {
                    int code = cand[p * CAP + ci];
                    const float* wr = w + (size_t)code * EDIM;
                    float szl = 0.f, dot = 0.f;
#pragma unroll 8
                    for (int k = 0; k < EDIM; k++) {
                        float zv = zr[k];
                        szl = __fadd_rn(szl, __fmul_rn(zv, zv));   // exact chain
                        dot = fmaf(zv, wr[k], dot);                // exact chain
                    }
                    float d = __fsub_rn(__fadd_rn(szl, sw_s[code]),
                                        __fmul_rn(2.f, dot));
                    unsigned long long pk =
                        ((unsigned long long)encF(d) << 32) | (uint32_t)code;
                    atomicMin(&best[p], pk);
                }
            } else {   // overflow fallback (≈never): exact full scan
                for (int code = q; code < NE; code += 8) {
                    const float* wr = w + (size_t)code * EDIM;
                    float szl = 0.f, dot = 0.f;
#pragma unroll 8
                    for (int k = 0; k < EDIM; k++) {
                        float zv = zr[k];
                        szl = __fadd_rn(szl, __fmul_rn(zv, zv));
                        dot = fmaf(zv, wr[k], dot);
                    }
                    float d = __fsub_rn(__fadd_rn(szl, sw_s[code]),
                                        __fmul_rn(2.f, dot));
                    unsigned long long pk =
                        ((unsigned long long)encF(d) << 32) | (uint32_t)code;
                    atomicMin(&best[p], pk);
                }
            }
        }
    }
    __syncthreads();
    if (tid < 64) {
        int cnt = ccnt[tid];
        int bc = (cnt == 1) ? cand[tid * CAP] : (int)(best[tid] & 0xFFFFFFFFu);
        g_idx[n0 + tid] = bc;
        out[OUT_IDX + n0 + tid] = (float)bc;
        atomicAdd(&g_counts[bc], 1);
    }
}

// ======================= gather: z_q_out (STE) + loss =======================
__global__ __launch_bounds__(256) void gather_kernel(const float* __restrict__ z,
                                                     const float* __restrict__ w,
                                                     float* __restrict__ out) {
    __shared__ float wrow[32][257];
    __shared__ int ids[32];
    __shared__ float red[8];
    int t = threadIdx.x, lane = t & 31, wrp = t >> 5;
    int n0 = blockIdx.x * 32;
    int b = n0 >> 10, hw0 = n0 & 1023;

    if (t < 32) ids[t] = g_idx[n0 + t];
    __syncthreads();
#pragma unroll
    for (int i = 0; i < 8; i++) {
        int idx = t + i * 256;
        int r = idx >> 6, q = idx & 63;
        float4 v = *(const float4*)(w + (size_t)ids[r] * 256 + q * 4);
        wrow[r][q * 4 + 0] = v.x; wrow[r][q * 4 + 1] = v.y;
        wrow[r][q * 4 + 2] = v.z; wrow[r][q * 4 + 3] = v.w;
    }
    __syncthreads();

    float loss = 0.f;
    const float* zb = z + (size_t)b * 262144 + hw0;
    float* ob = out + OUT_ZQ + (size_t)b * 262144 + hw0;
    for (int c = wrp; c < 256; c += 8) {
        float zv = zb[(size_t)c * 1024 + lane];
        float q = wrow[lane][c];
        float d = __fsub_rn(q, zv);
        ob[(size_t)c * 1024 + lane] = __fadd_rn(zv, d);
        loss += d * d;
    }
#pragma unroll
    for (int off = 16; off; off >>= 1) loss += __shfl_down_sync(0xffffffffu, loss, off);
    if (lane == 0) red[wrp] = loss;
    __syncthreads();
    if (wrp == 0) {
        float v = (lane < 8) ? red[lane] : 0.f;
#pragma unroll
        for (int off = 4; off; off >>= 1) v += __shfl_down_sync(0xffffffffu, v, off);
        if (lane == 0) atomicAdd(&g_loss_sum, v);
    }
}

// ======================= finalize =======================
__global__ void finalize_kernel(float* __restrict__ out) {
    int t = threadIdx.x;
    float em = (float)g_counts[t] * (1.0f / 32768.f);
    float s = em * logf(em + 1e-10f);
#pragma unroll
    for (int off = 16; off; off >>= 1) s += __shfl_down_sync(0xffffffffu, s, off);
    __shared__ float red[32];
    int lane = t & 31, wid = t >> 5;
    if (lane == 0) red[wid] = s;
    __syncthreads();
    if (wid == 0) {
        float v = red[lane];
#pragma unroll
        for (int off = 16; off; off >>= 1) v += __shfl_down_sync(0xffffffffu, v, off);
        if (lane == 0) {
            out[0] = g_loss_sum * (1.25f / 8388608.f);
            out[OUT_PERP] = expf(-v);
        }
    }
}

// ======================= launch =======================
extern "C" void kernel_launch(void* const* d_in, const int* in_sizes, int n_in,
                              void* d_out, int out_size) {
    const float* z = (const float*)d_in[0];
    const float* w = (const float*)d_in[1];
    float* out = (float*)d_out;

    cudaFuncSetAttribute(mma_kernel, cudaFuncAttributeMaxDynamicSharedMemorySize, SMEM_MMA);

    transpose_kernel<<<NPTS / 32, 256>>>(z);
    enorm_kernel<<<4, 256>>>(w);
    mma_kernel<<<NPTS / TM, 512, SMEM_MMA>>>(w, out);
    gather_kernel<<<NPTS / 32, 256>>>(z, w, out);
    finalize_kernel<<<1, 1024>>>(out);
}